// round 8
// baseline (speedup 1.0000x reference)
#include <cuda_runtime.h>
#include <cuda_bf16.h>

// Haar 2x2 DWT: x[16,64,256,256] f32 -> out[16,256,128,128] f32
//   out[n][k*C + c][h2][w2]
//   k0 = .5(a+b+cc+d); k1 = .5(a+b-cc-d); k2 = .5(a-b+cc-d); k3 = .5(a-b-cc+d)
//
// Round 8: champion config (__ldg loads, __stwt stores, one tile/thread),
// single change: block 256 -> 512 (grid 8192). Coarser CTA granularity,
// identical warp population and per-thread work.

#define N_   16
#define C_   64
#define H_   256
#define W_   256
#define H2_  (H_/2)   // 128
#define W2_  (W_/2)   // 128
#define W4IN (W_/4)   // 64 float4 per input row
#define W4OUT (W2_/4) // 32 float4 per output row
#define TPATCH 32     // threads per row-pair: W_/8
#define BLOCK_THREADS 512

__global__ __launch_bounds__(BLOCK_THREADS, 4)
void dwt2_haar_kernel(const float* __restrict__ x, float* __restrict__ out) {
    unsigned tid = blockIdx.x * BLOCK_THREADS + threadIdx.x;
    // tid = ((n*C_ + c)*H2_ + h2)*TPATCH + w8
    unsigned w8   = tid & (TPATCH - 1);
    unsigned rest = tid >> 5;
    unsigned h2   = rest & (H2_ - 1);
    rest >>= 7;
    unsigned c    = rest & (C_ - 1);
    unsigned n    = rest >> 6;

    const float4* xv = (const float4*)x;
    unsigned row0 = (n * C_ + c) * H_ + 2u * h2;
    unsigned ib   = row0 * W4IN + w8 * 2u;

    float4 t0 = __ldg(&xv[ib]);
    float4 t1 = __ldg(&xv[ib + 1]);
    float4 b0 = __ldg(&xv[ib + W4IN]);
    float4 b1 = __ldg(&xv[ib + 1 + W4IN]);

    float4 o0, o1, o2, o3;  // subbands k=0..3, 4 output cols each

    {
        float a = t0.x, b = t0.y, cc = b0.x, d = b0.y;
        float s0 = a + b, s1 = cc + d, e0 = a - b, e1 = cc - d;
        o0.x = 0.5f*(s0+s1); o1.x = 0.5f*(s0-s1); o2.x = 0.5f*(e0+e1); o3.x = 0.5f*(e0-e1);
    }
    {
        float a = t0.z, b = t0.w, cc = b0.z, d = b0.w;
        float s0 = a + b, s1 = cc + d, e0 = a - b, e1 = cc - d;
        o0.y = 0.5f*(s0+s1); o1.y = 0.5f*(s0-s1); o2.y = 0.5f*(e0+e1); o3.y = 0.5f*(e0-e1);
    }
    {
        float a = t1.x, b = t1.y, cc = b1.x, d = b1.y;
        float s0 = a + b, s1 = cc + d, e0 = a - b, e1 = cc - d;
        o0.z = 0.5f*(s0+s1); o1.z = 0.5f*(s0-s1); o2.z = 0.5f*(e0+e1); o3.z = 0.5f*(e0-e1);
    }
    {
        float a = t1.z, b = t1.w, cc = b1.z, d = b1.w;
        float s0 = a + b, s1 = cc + d, e0 = a - b, e1 = cc - d;
        o0.w = 0.5f*(s0+s1); o1.w = 0.5f*(s0-s1); o2.w = 0.5f*(e0+e1); o3.w = 0.5f*(e0-e1);
    }

    float4* ov = (float4*)out;
    unsigned plane = n * (4u * C_) + c;                 // k=0 plane
    unsigned ob = (plane * H2_ + h2) * W4OUT + w8;
    const unsigned kstride = C_ * H2_ * W4OUT;

    __stwt(&ov[ob],              o0);
    __stwt(&ov[ob + kstride],    o1);
    __stwt(&ov[ob + 2u*kstride], o2);
    __stwt(&ov[ob + 3u*kstride], o3);
}

extern "C" void kernel_launch(void* const* d_in, const int* in_sizes, int n_in,
                              void* d_out, int out_size) {
    const float* x = (const float*)d_in[0];
    float* out = (float*)d_out;
    const unsigned total = N_ * C_ * H2_ * TPATCH;   // 4,194,304 threads
    dwt2_haar_kernel<<<total / BLOCK_THREADS, BLOCK_THREADS>>>(x, out);
}

// round 9
// speedup vs baseline: 1.0016x; 1.0016x over previous
#include <cuda_runtime.h>
#include <cuda_bf16.h>

// Haar 2x2 DWT: x[16,64,256,256] f32 -> out[16,256,128,128] f32
//   out[n][k*C + c][h2][w2]
//   k0 = .5(a+b+cc+d); k1 = .5(a+b-cc-d); k2 = .5(a-b+cc-d); k3 = .5(a-b-cc+d)
//
// Round 9: champion config (__ldg loads, __stwt stores, one tile/thread),
// final scheduling probe: block 512 -> 1024 (grid 4096). DRAM% trended up
// with coarser CTA granularity (256: 80.4%, 512: 81.6%).

#define N_   16
#define C_   64
#define H_   256
#define W_   256
#define H2_  (H_/2)   // 128
#define W2_  (W_/2)   // 128
#define W4IN (W_/4)   // 64 float4 per input row
#define W4OUT (W2_/4) // 32 float4 per output row
#define TPATCH 32     // threads per row-pair: W_/8
#define BLOCK_THREADS 1024

__global__ __launch_bounds__(BLOCK_THREADS, 2)
void dwt2_haar_kernel(const float* __restrict__ x, float* __restrict__ out) {
    unsigned tid = blockIdx.x * BLOCK_THREADS + threadIdx.x;
    // tid = ((n*C_ + c)*H2_ + h2)*TPATCH + w8
    unsigned w8   = tid & (TPATCH - 1);
    unsigned rest = tid >> 5;
    unsigned h2   = rest & (H2_ - 1);
    rest >>= 7;
    unsigned c    = rest & (C_ - 1);
    unsigned n    = rest >> 6;

    const float4* xv = (const float4*)x;
    unsigned row0 = (n * C_ + c) * H_ + 2u * h2;
    unsigned ib   = row0 * W4IN + w8 * 2u;

    float4 t0 = __ldg(&xv[ib]);
    float4 t1 = __ldg(&xv[ib + 1]);
    float4 b0 = __ldg(&xv[ib + W4IN]);
    float4 b1 = __ldg(&xv[ib + 1 + W4IN]);

    float4 o0, o1, o2, o3;  // subbands k=0..3, 4 output cols each

    {
        float a = t0.x, b = t0.y, cc = b0.x, d = b0.y;
        float s0 = a + b, s1 = cc + d, e0 = a - b, e1 = cc - d;
        o0.x = 0.5f*(s0+s1); o1.x = 0.5f*(s0-s1); o2.x = 0.5f*(e0+e1); o3.x = 0.5f*(e0-e1);
    }
    {
        float a = t0.z, b = t0.w, cc = b0.z, d = b0.w;
        float s0 = a + b, s1 = cc + d, e0 = a - b, e1 = cc - d;
        o0.y = 0.5f*(s0+s1); o1.y = 0.5f*(s0-s1); o2.y = 0.5f*(e0+e1); o3.y = 0.5f*(e0-e1);
    }
    {
        float a = t1.x, b = t1.y, cc = b1.x, d = b1.y;
        float s0 = a + b, s1 = cc + d, e0 = a - b, e1 = cc - d;
        o0.z = 0.5f*(s0+s1); o1.z = 0.5f*(s0-s1); o2.z = 0.5f*(e0+e1); o3.z = 0.5f*(e0-e1);
    }
    {
        float a = t1.z, b = t1.w, cc = b1.z, d = b1.w;
        float s0 = a + b, s1 = cc + d, e0 = a - b, e1 = cc - d;
        o0.w = 0.5f*(s0+s1); o1.w = 0.5f*(s0-s1); o2.w = 0.5f*(e0+e1); o3.w = 0.5f*(e0-e1);
    }

    float4* ov = (float4*)out;
    unsigned plane = n * (4u * C_) + c;                 // k=0 plane
    unsigned ob = (plane * H2_ + h2) * W4OUT + w8;
    const unsigned kstride = C_ * H2_ * W4OUT;

    __stwt(&ov[ob],              o0);
    __stwt(&ov[ob + kstride],    o1);
    __stwt(&ov[ob + 2u*kstride], o2);
    __stwt(&ov[ob + 3u*kstride], o3);
}

extern "C" void kernel_launch(void* const* d_in, const int* in_sizes, int n_in,
                              void* d_out, int out_size) {
    const float* x = (const float*)d_in[0];
    float* out = (float*)d_out;
    const unsigned total = N_ * C_ * H2_ * TPATCH;   // 4,194,304 threads
    dwt2_haar_kernel<<<total / BLOCK_THREADS, BLOCK_THREADS>>>(x, out);
}